// round 6
// baseline (speedup 1.0000x reference)
#include <cuda_runtime.h>
#include <cstdint>

// Problem dims
#define B_DIM 16384
#define K_DIM 256
#define N_DIM 4096

// Tile config: CTA 256x256, 512 threads, warp grid 4(M) x 4(N), warp tile 64x64
#define BM 256
#define BN 256
#define BK 32                       // fp32 per K-chunk (one 128B permuted row-chunk)
#define NCHUNK (K_DIM / BK)         // 8
#define NSTAGE 3
#define A_STAGE_BYTES (BM * 128)    // 32 KB
#define B_STAGE_BYTES (BN * 128)    // 32 KB
#define STAGE_BYTES (A_STAGE_BYTES + B_STAGE_BYTES)  // 64 KB
#define SMEM_TOTAL (NSTAGE * STAGE_BYTES)            // 192 KB

// Scratch: tf32-rounded, K-permuted copies of x and W.
// Permuted K within each 32-chunk: kp = (k%4)*8 + (k%32)/4  (i.e. k = t*4+cc, kp = cc*8+t).
// Makes every mma fragment gather a single ld.shared.v4.b32.
__device__ float g_xt[B_DIM * K_DIM];   // [B][Kperm]
__device__ float g_w2[N_DIM * K_DIM];   // [N][Kperm], source W[s][o][cg], k = s*8+cg

// ---------------- helpers ----------------
static __device__ __forceinline__ uint32_t smem_u32(const void* p) {
    uint32_t a;
    asm("{ .reg .u64 t; cvta.to.shared.u64 t, %1; cvt.u32.u64 %0, t; }" : "=r"(a) : "l"(p));
    return a;
}
static __device__ __forceinline__ float tf32_rna(float v) {
    uint32_t u;
    asm("cvt.rna.tf32.f32 %0, %1;" : "=r"(u) : "f"(v));
    return __uint_as_float(u);
}
static __device__ __forceinline__ void lds128(uint32_t* r, uint32_t addr) {
    asm volatile("ld.shared.v4.b32 {%0,%1,%2,%3}, [%4];"
                 : "=r"(r[0]), "=r"(r[1]), "=r"(r[2]), "=r"(r[3]) : "r"(addr));
}
static __device__ __forceinline__ void mma8(float* d,
                                            uint32_t a0, uint32_t a1, uint32_t a2, uint32_t a3,
                                            uint32_t b0, uint32_t b1) {
    asm volatile(
        "mma.sync.aligned.m16n8k8.row.col.f32.tf32.tf32.f32 "
        "{%0,%1,%2,%3}, {%4,%5,%6,%7}, {%8,%9}, {%0,%1,%2,%3};"
        : "+f"(d[0]), "+f"(d[1]), "+f"(d[2]), "+f"(d[3])
        : "r"(a0), "r"(a1), "r"(a2), "r"(a3), "r"(b0), "r"(b1));
}
static __device__ __forceinline__ void cp16(uint32_t dst, const void* src) {
    asm volatile("cp.async.cg.shared.global [%0], [%1], 16;" :: "r"(dst), "l"(src) : "memory");
}

// Load one K-chunk (A: 256x32, B: 256x32 permuted floats) into a stage.
// 16B-chunk XOR swizzle by (row & 7) -> conflict-free fragment lds.128.
static __device__ __forceinline__ void load_chunk(int tid, int m0, int n0, int kc, uint32_t stage) {
#pragma unroll
    for (int i = 0; i < 4; i++) {          // A: 2048 16B chunks / 512 threads
        int id = tid + i * 512;
        int m = id >> 3, w = id & 7;
        const float* src = g_xt + (size_t)(m0 + m) * K_DIM + kc * BK + w * 4;
        uint32_t dst = stage + (uint32_t)(m * 128 + ((w ^ (m & 7)) << 4));
        cp16(dst, src);
    }
#pragma unroll
    for (int i = 0; i < 4; i++) {          // B: 2048 16B chunks
        int id = tid + i * 512;
        int n = id >> 3, w = id & 7;
        const float* src = g_w2 + (size_t)(n0 + n) * K_DIM + kc * BK + w * 4;
        uint32_t dst = stage + A_STAGE_BYTES + (uint32_t)(n * 128 + ((w ^ (n & 7)) << 4));
        cp16(dst, src);
    }
    asm volatile("cp.async.commit_group;" ::: "memory");
}

// ---------------- repack kernels (tf32 RNA + K-permute, 4 elems/thread) ----------------
__global__ void __launch_bounds__(256) repack_x_k(const float* __restrict__ x) {
    int o = blockIdx.x * blockDim.x + threadIdx.x;    // over B*K/4 output float4s
    int b = o >> 6, kq = o & 63;
    int kp0 = kq * 4;
    int kin = kp0 & 31, cc = kin >> 3, t0 = kin & 7, kb = (kp0 & ~31);
    const float* xr = x + b * K_DIM + kb + cc;
    float4 v;
    v.x = tf32_rna(xr[(t0 + 0) * 4]);
    v.y = tf32_rna(xr[(t0 + 1) * 4]);
    v.z = tf32_rna(xr[(t0 + 2) * 4]);
    v.w = tf32_rna(xr[(t0 + 3) * 4]);
    reinterpret_cast<float4*>(g_xt)[o] = v;
}
__global__ void __launch_bounds__(256) repack_w_k(const float* __restrict__ W) {
    int o = blockIdx.x * blockDim.x + threadIdx.x;    // over N*K/4 output float4s
    int n = o >> 6, kq = o & 63;
    int kp0 = kq * 4;
    int kin = kp0 & 31, cc = kin >> 3, t0 = kin & 7, kb = (kp0 & ~31);
    float4 v;
#pragma unroll
    for (int j = 0; j < 4; j++) {
        int k = kb + (t0 + j) * 4 + cc;
        int s = k >> 3, cg = k & 7;
        (&v.x)[j] = tf32_rna(W[s * (N_DIM * 8) + n * 8 + cg]);
    }
    reinterpret_cast<float4*>(g_w2)[o] = v;
}

// ---------------- main GEMM kernel ----------------
__global__ void __launch_bounds__(512, 1) slb_gemm(float* __restrict__ out) {
    extern __shared__ char smem[];
    const uint32_t sb = smem_u32(smem);
    const int tid = threadIdx.x;
    const int lane = tid & 31;
    const int wid = tid >> 5;
    const int g = lane >> 2;          // fragment group row
    const int c = lane & 3;           // fragment group col
    const int wm = wid & 3;           // warp M index (4)
    const int wn = wid >> 2;          // warp N index (4)

    const int m0 = (int)(blockIdx.x >> 4) * BM;   // 64 m-tiles
    const int n0 = (int)(blockIdx.x & 15) * BN;   // 16 n-tiles (n-minor for L2 reuse)

    float acc[4][8][4];
#pragma unroll
    for (int mt = 0; mt < 4; mt++)
#pragma unroll
        for (int nt = 0; nt < 8; nt++)
#pragma unroll
            for (int e = 0; e < 4; e++) acc[mt][nt][e] = 0.0f;

    // Prologue: chunks 0,1
    load_chunk(tid, m0, n0, 0, sb);
    load_chunk(tid, m0, n0, 1, sb + STAGE_BYTES);

    // Per-thread row byte offsets (relative to stage base)
    uint32_t arel[8], brel[8];
#pragma unroll
    for (int rg = 0; rg < 8; rg++) arel[rg] = (uint32_t)((wm * 64 + g + rg * 8) * 128);
#pragma unroll
    for (int nt = 0; nt < 8; nt++)
        brel[nt] = (uint32_t)(A_STAGE_BYTES + (wn * 64 + nt * 8 + g) * 128);

#pragma unroll
    for (int kc = 0; kc < NCHUNK; kc++) {
        if (kc < NCHUNK - 1) asm volatile("cp.async.wait_group 1;" ::: "memory");
        else                 asm volatile("cp.async.wait_group 0;" ::: "memory");
        __syncthreads();
        if (kc + 2 < NCHUNK)
            load_chunk(tid, m0, n0, kc + 2, sb + (uint32_t)(((kc + 2) % NSTAGE) * STAGE_BYTES));

        const uint32_t st = sb + (uint32_t)((kc % NSTAGE) * STAGE_BYTES);
#pragma unroll
        for (int jh = 0; jh < 2; jh++) {
            const uint32_t chk = (uint32_t)(((2 * c + jh) ^ g) << 4);
            uint32_t a[8][4];
#pragma unroll
            for (int rg = 0; rg < 8; rg++) lds128(a[rg], st + arel[rg] + chk);
#pragma unroll
            for (int nh = 0; nh < 2; nh++) {
                uint32_t b[4][4];
#pragma unroll
                for (int q = 0; q < 4; q++) lds128(b[q], st + brel[nh * 4 + q] + chk);
#pragma unroll
                for (int j2 = 0; j2 < 2; j2++)
#pragma unroll
                    for (int mt = 0; mt < 4; mt++)
#pragma unroll
                        for (int q = 0; q < 4; q++)
                            mma8(acc[mt][nh * 4 + q],
                                 a[2 * mt][2 * j2], a[2 * mt + 1][2 * j2],
                                 a[2 * mt][2 * j2 + 1], a[2 * mt + 1][2 * j2 + 1],
                                 b[q][2 * j2], b[q][2 * j2 + 1]);
            }
        }
    }

    // ---- Epilogue: direct sector-aligned STG.64 from register accumulators ----
    float* op = out + (size_t)(m0 + wm * 64 + g) * N_DIM + (n0 + wn * 64 + 2 * c);
#pragma unroll
    for (int mt = 0; mt < 4; mt++) {
#pragma unroll
        for (int nt = 0; nt < 8; nt++) {
            float2 v0 = make_float2(acc[mt][nt][0], acc[mt][nt][1]);
            float2 v1 = make_float2(acc[mt][nt][2], acc[mt][nt][3]);
            *reinterpret_cast<float2*>(op + (size_t)(mt * 16) * N_DIM + nt * 8) = v0;
            *reinterpret_cast<float2*>(op + (size_t)(mt * 16 + 8) * N_DIM + nt * 8) = v1;
        }
    }
}

// ---------------- launch ----------------
extern "C" void kernel_launch(void* const* d_in, const int* in_sizes, int n_in,
                              void* d_out, int out_size) {
    const float* x = (const float*)d_in[0];
    const float* W = (const float*)d_in[1];
    if (n_in >= 2 && in_sizes[0] == N_DIM * K_DIM && in_sizes[1] == B_DIM * K_DIM) {
        const float* t = x; x = W; W = t;   // defensive order swap
    }
    cudaFuncSetAttribute(slb_gemm, cudaFuncAttributeMaxDynamicSharedMemorySize, SMEM_TOTAL);

    repack_x_k<<<(B_DIM * K_DIM / 4) / 256, 256>>>(x);
    repack_w_k<<<(N_DIM * K_DIM / 4) / 256, 256>>>(W);
    slb_gemm<<<(B_DIM / BM) * (N_DIM / BN), 512, SMEM_TOTAL>>>((float*)d_out);
}

// round 10
// speedup vs baseline: 2.7276x; 2.7276x over previous
#include <cuda_runtime.h>
#include <cstdint>

// Problem dims
#define B_DIM 16384
#define K_DIM 256
#define N_DIM 4096

// Tile config: CTA 256x128, 512 threads, warp grid 8(M) x 2(N), warp tile 32x64
#define BM 256
#define BN 128
#define BK 32                       // fp32 per K-chunk (one 128B permuted row-chunk)
#define NCHUNK (K_DIM / BK)         // 8
#define NSTAGE 3
#define A_STAGE_BYTES (BM * 128)    // 32 KB
#define B_STAGE_BYTES (BN * 128)    // 16 KB
#define STAGE_BYTES (A_STAGE_BYTES + B_STAGE_BYTES)  // 48 KB
#define SMEM_TOTAL (NSTAGE * STAGE_BYTES)            // 144 KB

// Scratch: tf32-rounded, K-permuted copies of x and W.
// Permuted K within each 32-chunk: kp = (k%4)*8 + (k%32)/4  (k = t*4+cc -> kp = cc*8+t).
// Makes every mma fragment gather a single ld.shared.v4.b32.
__device__ float g_xt[B_DIM * K_DIM];   // [B][Kperm]
__device__ float g_w2[N_DIM * K_DIM];   // [N][Kperm], source W[s][o][cg], k = s*8+cg

// ---------------- helpers ----------------
static __device__ __forceinline__ uint32_t smem_u32(const void* p) {
    uint32_t a;
    asm("{ .reg .u64 t; cvta.to.shared.u64 t, %1; cvt.u32.u64 %0, t; }" : "=r"(a) : "l"(p));
    return a;
}
static __device__ __forceinline__ float tf32_rna(float v) {
    uint32_t u;
    asm("cvt.rna.tf32.f32 %0, %1;" : "=r"(u) : "f"(v));
    return __uint_as_float(u);
}
static __device__ __forceinline__ void lds128(uint32_t* r, uint32_t addr) {
    asm volatile("ld.shared.v4.b32 {%0,%1,%2,%3}, [%4];"
                 : "=r"(r[0]), "=r"(r[1]), "=r"(r[2]), "=r"(r[3]) : "r"(addr));
}
static __device__ __forceinline__ void mma8(float* d,
                                            uint32_t a0, uint32_t a1, uint32_t a2, uint32_t a3,
                                            uint32_t b0, uint32_t b1) {
    asm volatile(
        "mma.sync.aligned.m16n8k8.row.col.f32.tf32.tf32.f32 "
        "{%0,%1,%2,%3}, {%4,%5,%6,%7}, {%8,%9}, {%0,%1,%2,%3};"
        : "+f"(d[0]), "+f"(d[1]), "+f"(d[2]), "+f"(d[3])
        : "r"(a0), "r"(a1), "r"(a2), "r"(a3), "r"(b0), "r"(b1));
}
static __device__ __forceinline__ void cp16(uint32_t dst, const void* src) {
    asm volatile("cp.async.cg.shared.global [%0], [%1], 16;" :: "r"(dst), "l"(src) : "memory");
}

// Load one K-chunk (A: 256x32, B: 128x32 permuted floats) into a stage.
// 16B-chunk XOR swizzle by (row & 7) -> conflict-free fragment lds.128.
static __device__ __forceinline__ void load_chunk(int tid, int m0, int n0, int kc, uint32_t stage) {
#pragma unroll
    for (int i = 0; i < 4; i++) {          // A: 2048 16B chunks / 512 threads
        int id = tid + i * 512;
        int m = id >> 3, w = id & 7;
        const float* src = g_xt + (size_t)(m0 + m) * K_DIM + kc * BK + w * 4;
        uint32_t dst = stage + (uint32_t)(m * 128 + ((w ^ (m & 7)) << 4));
        cp16(dst, src);
    }
#pragma unroll
    for (int i = 0; i < 2; i++) {          // B: 1024 16B chunks
        int id = tid + i * 512;
        int n = id >> 3, w = id & 7;
        const float* src = g_w2 + (size_t)(n0 + n) * K_DIM + kc * BK + w * 4;
        uint32_t dst = stage + A_STAGE_BYTES + (uint32_t)(n * 128 + ((w ^ (n & 7)) << 4));
        cp16(dst, src);
    }
    asm volatile("cp.async.commit_group;" ::: "memory");
}

// ---------------- fused repack kernel (tf32 RNA + K-permute, 1 float4/thread) ----------------
// Blocks [0, XBLKS) handle x; blocks [XBLKS, XBLKS+WBLKS) handle W.
#define XBLKS ((B_DIM * K_DIM / 4) / 256)   // 4096
#define WBLKS ((N_DIM * K_DIM / 4) / 256)   // 1024
__global__ void __launch_bounds__(256) repack_all(const float* __restrict__ x,
                                                  const float* __restrict__ W) {
    int bx = blockIdx.x;
    if (bx < XBLKS) {
        int o = bx * 256 + threadIdx.x;               // over B*K/4 output float4s
        int b = o >> 6, kq = o & 63;
        int kp0 = kq * 4;
        int kin = kp0 & 31, cc = kin >> 3, t0 = kin & 7, kb = (kp0 & ~31);
        const float* xr = x + b * K_DIM + kb + cc;
        float4 v;
        v.x = tf32_rna(xr[(t0 + 0) * 4]);
        v.y = tf32_rna(xr[(t0 + 1) * 4]);
        v.z = tf32_rna(xr[(t0 + 2) * 4]);
        v.w = tf32_rna(xr[(t0 + 3) * 4]);
        reinterpret_cast<float4*>(g_xt)[o] = v;
    } else {
        int o = (bx - XBLKS) * 256 + threadIdx.x;     // over N*K/4 output float4s
        int n = o >> 6, kq = o & 63;
        int kp0 = kq * 4;
        int kin = kp0 & 31, cc = kin >> 3, t0 = kin & 7, kb = (kp0 & ~31);
        float4 v;
#pragma unroll
        for (int j = 0; j < 4; j++) {
            int k = kb + (t0 + j) * 4 + cc;
            int s = k >> 3, cg = k & 7;
            (&v.x)[j] = tf32_rna(W[s * (N_DIM * 8) + n * 8 + cg]);
        }
        reinterpret_cast<float4*>(g_w2)[o] = v;
    }
}

// ---------------- main GEMM kernel ----------------
__global__ void __launch_bounds__(512, 1) slb_gemm(float* __restrict__ out) {
    extern __shared__ char smem[];
    const uint32_t sb = smem_u32(smem);
    const int tid = threadIdx.x;
    const int lane = tid & 31;
    const int wid = tid >> 5;
    const int g = lane >> 2;          // fragment group row
    const int c = lane & 3;           // fragment group col
    const int wm = wid & 7;           // warp M index (8)
    const int wn = wid >> 3;          // warp N index (2)

    // m-minor rasterization: consecutive bids sweep M with fixed N tile ->
    // x stays L2-resident across the whole n sweep.
    const int m0 = (int)(blockIdx.x & 63) * BM;   // 64 m-tiles
    const int n0 = (int)(blockIdx.x >> 6) * BN;   // 32 n-tiles

    float acc[2][8][4];
#pragma unroll
    for (int mt = 0; mt < 2; mt++)
#pragma unroll
        for (int nt = 0; nt < 8; nt++)
#pragma unroll
            for (int e = 0; e < 4; e++) acc[mt][nt][e] = 0.0f;

    // Prologue: chunks 0,1
    load_chunk(tid, m0, n0, 0, sb);
    load_chunk(tid, m0, n0, 1, sb + STAGE_BYTES);

    // Per-thread row byte offsets (relative to stage base)
    uint32_t arel[4], brel[8];
#pragma unroll
    for (int rg = 0; rg < 4; rg++) arel[rg] = (uint32_t)((wm * 32 + g + rg * 8) * 128);
#pragma unroll
    for (int nt = 0; nt < 8; nt++)
        brel[nt] = (uint32_t)(A_STAGE_BYTES + (wn * 64 + nt * 8 + g) * 128);

#pragma unroll
    for (int kc = 0; kc < NCHUNK; kc++) {
        if (kc < NCHUNK - 1) asm volatile("cp.async.wait_group 1;" ::: "memory");
        else                 asm volatile("cp.async.wait_group 0;" ::: "memory");
        __syncthreads();
        if (kc + 2 < NCHUNK)
            load_chunk(tid, m0, n0, kc + 2, sb + (uint32_t)(((kc + 2) % NSTAGE) * STAGE_BYTES));

        const uint32_t st = sb + (uint32_t)((kc % NSTAGE) * STAGE_BYTES);
#pragma unroll
        for (int jh = 0; jh < 2; jh++) {
            const uint32_t chk = (uint32_t)(((2 * c + jh) ^ g) << 4);
            uint32_t a[4][4];
#pragma unroll
            for (int rg = 0; rg < 4; rg++) lds128(a[rg], st + arel[rg] + chk);
#pragma unroll
            for (int nh = 0; nh < 2; nh++) {
                uint32_t b[4][4];
#pragma unroll
                for (int q = 0; q < 4; q++) lds128(b[q], st + brel[nh * 4 + q] + chk);
#pragma unroll
                for (int j2 = 0; j2 < 2; j2++)
#pragma unroll
                    for (int mt = 0; mt < 2; mt++)
#pragma unroll
                        for (int q = 0; q < 4; q++)
                            mma8(acc[mt][nh * 4 + q],
                                 a[2 * mt][2 * j2], a[2 * mt + 1][2 * j2],
                                 a[2 * mt][2 * j2 + 1], a[2 * mt + 1][2 * j2 + 1],
                                 b[q][2 * j2], b[q][2 * j2 + 1]);
            }
        }
    }

    // ---- Epilogue: direct sector-aligned STG.64 from register accumulators ----
    float* op = out + (size_t)(m0 + wm * 32 + g) * N_DIM + (n0 + wn * 64 + 2 * c);
#pragma unroll
    for (int mt = 0; mt < 2; mt++) {
#pragma unroll
        for (int nt = 0; nt < 8; nt++) {
            float2 v0 = make_float2(acc[mt][nt][0], acc[mt][nt][1]);
            float2 v1 = make_float2(acc[mt][nt][2], acc[mt][nt][3]);
            *reinterpret_cast<float2*>(op + (size_t)(mt * 16) * N_DIM + nt * 8) = v0;
            *reinterpret_cast<float2*>(op + (size_t)(mt * 16 + 8) * N_DIM + nt * 8) = v1;
        }
    }
}

// ---------------- launch ----------------
extern "C" void kernel_launch(void* const* d_in, const int* in_sizes, int n_in,
                              void* d_out, int out_size) {
    const float* x = (const float*)d_in[0];
    const float* W = (const float*)d_in[1];
    if (n_in >= 2 && in_sizes[0] == N_DIM * K_DIM && in_sizes[1] == B_DIM * K_DIM) {
        const float* t = x; x = W; W = t;   // defensive order swap
    }
    cudaFuncSetAttribute(slb_gemm, cudaFuncAttributeMaxDynamicSharedMemorySize, SMEM_TOTAL);

    repack_all<<<XBLKS + WBLKS, 256>>>(x, W);
    slb_gemm<<<(B_DIM / BM) * (N_DIM / BN), 512, SMEM_TOTAL>>>((float*)d_out);
}

// round 11
// speedup vs baseline: 2.7568x; 1.0107x over previous
#include <cuda_runtime.h>
#include <cstdint>

// Problem dims
#define B_DIM 16384
#define K_DIM 256
#define N_DIM 4096

// Tile config: CTA 256x128, 512 threads, warp grid 8(M) x 2(N), warp tile 32x64
#define BM 256
#define BN 128
#define BK 32                       // fp32 per K-chunk (one 128B permuted row-chunk)
#define NCHUNK (K_DIM / BK)         // 8
#define NSTAGE 4
#define A_STAGE_BYTES (BM * 128)    // 32 KB
#define B_STAGE_BYTES (BN * 128)    // 16 KB
#define STAGE_BYTES (A_STAGE_BYTES + B_STAGE_BYTES)  // 48 KB
#define SMEM_TOTAL (NSTAGE * STAGE_BYTES)            // 192 KB

// Scratch: tf32-rounded, K-permuted copies of x and W.
// Permuted K within each 32-chunk: kp = (k%4)*8 + (k%32)/4  (k = t*4+cc -> kp = cc*8+t).
// Makes every mma fragment gather a single ld.shared.v4.b32.
__device__ float g_xt[B_DIM * K_DIM];   // [B][Kperm]
__device__ float g_w2[N_DIM * K_DIM];   // [N][Kperm], source W[s][o][cg], k = s*8+cg

// ---------------- helpers ----------------
static __device__ __forceinline__ uint32_t smem_u32(const void* p) {
    uint32_t a;
    asm("{ .reg .u64 t; cvta.to.shared.u64 t, %1; cvt.u32.u64 %0, t; }" : "=r"(a) : "l"(p));
    return a;
}
static __device__ __forceinline__ float tf32_rna(float v) {
    uint32_t u;
    asm("cvt.rna.tf32.f32 %0, %1;" : "=r"(u) : "f"(v));
    return __uint_as_float(u);
}
static __device__ __forceinline__ void lds128(uint32_t* r, uint32_t addr) {
    asm volatile("ld.shared.v4.b32 {%0,%1,%2,%3}, [%4];"
                 : "=r"(r[0]), "=r"(r[1]), "=r"(r[2]), "=r"(r[3]) : "r"(addr));
}
static __device__ __forceinline__ void mma8(float* d,
                                            uint32_t a0, uint32_t a1, uint32_t a2, uint32_t a3,
                                            uint32_t b0, uint32_t b1) {
    asm volatile(
        "mma.sync.aligned.m16n8k8.row.col.f32.tf32.tf32.f32 "
        "{%0,%1,%2,%3}, {%4,%5,%6,%7}, {%8,%9}, {%0,%1,%2,%3};"
        : "+f"(d[0]), "+f"(d[1]), "+f"(d[2]), "+f"(d[3])
        : "r"(a0), "r"(a1), "r"(a2), "r"(a3), "r"(b0), "r"(b1));
}
static __device__ __forceinline__ void cp16(uint32_t dst, const float* src) {
    asm volatile("cp.async.cg.shared.global [%0], [%1], 16;" :: "r"(dst), "l"(src) : "memory");
}

// ---------------- fused repack kernel (tf32 RNA + K-permute, 1 float4/thread) ----------------
#define XBLKS ((B_DIM * K_DIM / 4) / 256)   // 4096
#define WBLKS ((N_DIM * K_DIM / 4) / 256)   // 1024
__global__ void __launch_bounds__(256) repack_all(const float* __restrict__ x,
                                                  const float* __restrict__ W) {
    int bx = blockIdx.x;
    if (bx < XBLKS) {
        int o = bx * 256 + threadIdx.x;               // over B*K/4 output float4s
        int b = o >> 6, kq = o & 63;
        int kp0 = kq * 4;
        int kin = kp0 & 31, cc = kin >> 3, t0 = kin & 7, kb = (kp0 & ~31);
        const float* xr = x + b * K_DIM + kb + cc;
        float4 v;
        v.x = tf32_rna(xr[(t0 + 0) * 4]);
        v.y = tf32_rna(xr[(t0 + 1) * 4]);
        v.z = tf32_rna(xr[(t0 + 2) * 4]);
        v.w = tf32_rna(xr[(t0 + 3) * 4]);
        reinterpret_cast<float4*>(g_xt)[o] = v;
    } else {
        int o = (bx - XBLKS) * 256 + threadIdx.x;     // over N*K/4 output float4s
        int n = o >> 6, kq = o & 63;
        int kp0 = kq * 4;
        int kin = kp0 & 31, cc = kin >> 3, t0 = kin & 7, kb = (kp0 & ~31);
        float4 v;
#pragma unroll
        for (int j = 0; j < 4; j++) {
            int k = kb + (t0 + j) * 4 + cc;
            int s = k >> 3, cg = k & 7;
            (&v.x)[j] = tf32_rna(W[s * (N_DIM * 8) + n * 8 + cg]);
        }
        reinterpret_cast<float4*>(g_w2)[o] = v;
    }
}

// ---------------- main GEMM kernel ----------------
__global__ void __launch_bounds__(512, 1) slb_gemm(float* __restrict__ out) {
    extern __shared__ char smem[];
    const uint32_t sb = smem_u32(smem);
    const int tid = threadIdx.x;
    const int lane = tid & 31;
    const int wid = tid >> 5;
    const int g = lane >> 2;          // fragment group row
    const int c = lane & 3;           // fragment group col
    const int wm = wid & 7;           // warp M index (8)
    const int wn = wid >> 3;          // warp N index (2)

    // m-minor rasterization: consecutive bids sweep M with fixed N tile.
    const int m0 = (int)(blockIdx.x & 63) * BM;   // 64 m-tiles
    const int n0 = (int)(blockIdx.x >> 6) * BN;   // 32 n-tiles

    float acc[2][8][4];
#pragma unroll
    for (int mt = 0; mt < 2; mt++)
#pragma unroll
        for (int nt = 0; nt < 8; nt++)
#pragma unroll
            for (int e = 0; e < 4; e++) acc[mt][nt][e] = 0.0f;

    // Precomputed per-thread cp.async offsets (32-bit element offsets from array base,
    // advanced by kc*BK per chunk) and smem dst offsets (stage-relative).
    uint32_t aoff[4], adst[4], boff[2], bdst[2];
#pragma unroll
    for (int i = 0; i < 4; i++) {
        int id = tid + i * 512;
        int m = id >> 3, w = id & 7;
        aoff[i] = (uint32_t)((m0 + m) * K_DIM + w * 4);
        adst[i] = (uint32_t)(m * 128 + ((w ^ (m & 7)) << 4));
    }
#pragma unroll
    for (int i = 0; i < 2; i++) {
        int id = tid + i * 512;
        int n = id >> 3, w = id & 7;
        boff[i] = (uint32_t)((n0 + n) * K_DIM + w * 4);
        bdst[i] = (uint32_t)(A_STAGE_BYTES + n * 128 + ((w ^ (n & 7)) << 4));
    }

#define LOAD_CHUNK(kc)                                                          \
    {                                                                           \
        uint32_t stg_ = sb + (uint32_t)(((kc) & 3) * STAGE_BYTES);              \
        uint32_t ko_ = (uint32_t)((kc) * BK);                                   \
        cp16(stg_ + adst[0], g_xt + aoff[0] + ko_);                             \
        cp16(stg_ + adst[1], g_xt + aoff[1] + ko_);                             \
        cp16(stg_ + adst[2], g_xt + aoff[2] + ko_);                             \
        cp16(stg_ + adst[3], g_xt + aoff[3] + ko_);                             \
        cp16(stg_ + bdst[0], g_w2 + boff[0] + ko_);                             \
        cp16(stg_ + bdst[1], g_w2 + boff[1] + ko_);                             \
        asm volatile("cp.async.commit_group;" ::: "memory");                    \
    }

    // Prologue: chunks 0,1
    LOAD_CHUNK(0);
    LOAD_CHUNK(1);

    // Per-thread fragment row byte offsets (stage-relative)
    uint32_t arel[4], brel[8];
#pragma unroll
    for (int rg = 0; rg < 4; rg++) arel[rg] = (uint32_t)((wm * 32 + g + rg * 8) * 128);
#pragma unroll
    for (int nt = 0; nt < 8; nt++)
        brel[nt] = (uint32_t)(A_STAGE_BYTES + (wn * 64 + nt * 8 + g) * 128);

#pragma unroll
    for (int kc = 0; kc < NCHUNK; kc++) {
        // Early issue: next-next chunk's loads go out BEFORE we wait/sync.
        // Slot (kc+2)%4 was last read at iter kc-2; the sync at iter kc-1 orders it.
        if (kc + 2 < NCHUNK) LOAD_CHUNK(kc + 2);
        if (kc < NCHUNK - 2)      asm volatile("cp.async.wait_group 2;" ::: "memory");
        else if (kc == NCHUNK - 2) asm volatile("cp.async.wait_group 1;" ::: "memory");
        else                      asm volatile("cp.async.wait_group 0;" ::: "memory");
        __syncthreads();

        const uint32_t st = sb + (uint32_t)((kc & 3) * STAGE_BYTES);
#pragma unroll
        for (int jh = 0; jh < 2; jh++) {
            const uint32_t chk = (uint32_t)(((2 * c + jh) ^ g) << 4);
            // Batch all 12 fragment loads up front: one latency exposure, MLP=12.
            uint32_t a[4][4], b[8][4];
#pragma unroll
            for (int rg = 0; rg < 4; rg++) lds128(a[rg], st + arel[rg] + chk);
#pragma unroll
            for (int q = 0; q < 8; q++) lds128(b[q], st + brel[q] + chk);
#pragma unroll
            for (int nh = 0; nh < 2; nh++)
#pragma unroll
                for (int j2 = 0; j2 < 2; j2++)
#pragma unroll
                    for (int mt = 0; mt < 2; mt++)
#pragma unroll
                        for (int q = 0; q < 4; q++)
                            mma8(acc[mt][nh * 4 + q],
                                 a[2 * mt][2 * j2], a[2 * mt + 1][2 * j2],
                                 a[2 * mt][2 * j2 + 1], a[2 * mt + 1][2 * j2 + 1],
                                 b[nh * 4 + q][2 * j2], b[nh * 4 + q][2 * j2 + 1]);
        }
    }

    // ---- Epilogue: direct sector-aligned STG.64 from register accumulators ----
    float* op = out + (size_t)(m0 + wm * 32 + g) * N_DIM + (n0 + wn * 64 + 2 * c);
#pragma unroll
    for (int mt = 0; mt < 2; mt++) {
#pragma unroll
        for (int nt = 0; nt < 8; nt++) {
            float2 v0 = make_float2(acc[mt][nt][0], acc[mt][nt][1]);
            float2 v1 = make_float2(acc[mt][nt][2], acc[mt][nt][3]);
            *reinterpret_cast<float2*>(op + (size_t)(mt * 16) * N_DIM + nt * 8) = v0;
            *reinterpret_cast<float2*>(op + (size_t)(mt * 16 + 8) * N_DIM + nt * 8) = v1;
        }
    }
}

// ---------------- launch ----------------
extern "C" void kernel_launch(void* const* d_in, const int* in_sizes, int n_in,
                              void* d_out, int out_size) {
    const float* x = (const float*)d_in[0];
    const float* W = (const float*)d_in[1];
    if (n_in >= 2 && in_sizes[0] == N_DIM * K_DIM && in_sizes[1] == B_DIM * K_DIM) {
        const float* t = x; x = W; W = t;   // defensive order swap
    }
    cudaFuncSetAttribute(slb_gemm, cudaFuncAttributeMaxDynamicSharedMemorySize, SMEM_TOTAL);

    repack_all<<<XBLKS + WBLKS, 256>>>(x, W);
    slb_gemm<<<(B_DIM / BM) * (N_DIM / BN), 512, SMEM_TOTAL>>>((float*)d_out);
}

// round 12
// speedup vs baseline: 5.1026x; 1.8509x over previous
#include <cuda_runtime.h>
#include <cuda_fp16.h>
#include <cstdint>

// Problem dims
#define B_DIM 16384
#define K_DIM 256
#define N_DIM 4096

// Tile config: CTA 256x128, 512 threads, warp grid 8(M) x 2(N), warp tile 32x64
#define BM 256
#define BN 128
#define KC 64                       // fp16 per K-chunk (one 128B row per chunk)
#define NCHUNK (K_DIM / KC)         // 4 -> whole K prefetched, no ring reuse
#define A_STAGE_BYTES (BM * 128)    // 32 KB
#define B_STAGE_BYTES (BN * 128)    // 16 KB
#define STAGE_BYTES (A_STAGE_BYTES + B_STAGE_BYTES)  // 48 KB
#define SMEM_TOTAL (NCHUNK * STAGE_BYTES)            // 192 KB

// Scratch: fp16(RN) copies. g_wh is gathered to [N][K] row-major (k = s*8+cg).
__device__ __half g_xh[B_DIM * K_DIM];   // [B][K]
__device__ __half g_wh[N_DIM * K_DIM];   // [N][K]

// ---------------- helpers ----------------
static __device__ __forceinline__ uint32_t smem_u32(const void* p) {
    uint32_t a;
    asm("{ .reg .u64 t; cvta.to.shared.u64 t, %1; cvt.u32.u64 %0, t; }" : "=r"(a) : "l"(p));
    return a;
}
static __device__ __forceinline__ void ldsm4(uint32_t* r, uint32_t addr) {
    asm volatile("ldmatrix.sync.aligned.m8n8.x4.shared.b16 {%0,%1,%2,%3}, [%4];"
                 : "=r"(r[0]), "=r"(r[1]), "=r"(r[2]), "=r"(r[3]) : "r"(addr));
}
static __device__ __forceinline__ void mma16(float* d, const uint32_t* a, uint32_t b0, uint32_t b1) {
    asm volatile(
        "mma.sync.aligned.m16n8k16.row.col.f32.f16.f16.f32 "
        "{%0,%1,%2,%3}, {%4,%5,%6,%7}, {%8,%9}, {%0,%1,%2,%3};"
        : "+f"(d[0]), "+f"(d[1]), "+f"(d[2]), "+f"(d[3])
        : "r"(a[0]), "r"(a[1]), "r"(a[2]), "r"(a[3]), "r"(b0), "r"(b1));
}
static __device__ __forceinline__ void cp16(uint32_t dst, const __half* src) {
    asm volatile("cp.async.cg.shared.global [%0], [%1], 16;" :: "r"(dst), "l"(src) : "memory");
}

// ---------------- fused repack kernel (fp32 -> fp16 RN, W gather) ----------------
#define XBLKS ((B_DIM * K_DIM / 8) / 256)   // 2048  (8 elems/thread)
#define WBLKS ((N_DIM * K_DIM / 8) / 256)   // 512
__global__ void __launch_bounds__(256) repack_all(const float* __restrict__ x,
                                                  const float* __restrict__ W) {
    int bx = blockIdx.x;
    if (bx < XBLKS) {
        int o = bx * 256 + threadIdx.x;                // 8-float group over x
        const float4* xs = reinterpret_cast<const float4*>(x) + (size_t)o * 2;
        float4 v0 = xs[0], v1 = xs[1];
        __half2* dst = reinterpret_cast<__half2*>(g_xh) + (size_t)o * 4;
        dst[0] = __floats2half2_rn(v0.x, v0.y);
        dst[1] = __floats2half2_rn(v0.z, v0.w);
        dst[2] = __floats2half2_rn(v1.x, v1.y);
        dst[3] = __floats2half2_rn(v1.z, v1.w);
    } else {
        int o = (bx - XBLKS) * 256 + threadIdx.x;      // over N*K/8
        int n = o >> 5, sg = o & 31;                   // slice group s = sg, 8 contiguous cg
        const float* src = W + (size_t)sg * (N_DIM * 8) + (size_t)n * 8;
        float4 v0 = *reinterpret_cast<const float4*>(src);
        float4 v1 = *reinterpret_cast<const float4*>(src + 4);
        __half2* dst = reinterpret_cast<__half2*>(g_wh + (size_t)n * K_DIM + sg * 8);
        dst[0] = __floats2half2_rn(v0.x, v0.y);
        dst[1] = __floats2half2_rn(v0.z, v0.w);
        dst[2] = __floats2half2_rn(v1.x, v1.y);
        dst[3] = __floats2half2_rn(v1.z, v1.w);
    }
}

// ---------------- main GEMM kernel ----------------
__global__ void __launch_bounds__(512, 1) slb_gemm(float* __restrict__ out) {
    extern __shared__ char smem[];
    const uint32_t sb = smem_u32(smem);
    const int tid = threadIdx.x;
    const int lane = tid & 31;
    const int wid = tid >> 5;
    const int g = lane >> 2;          // output fragment row group
    const int c = lane & 3;           // output fragment col group
    const int wm = wid & 7;           // warp M index (8)
    const int wn = wid >> 3;          // warp N index (2)

    // m-minor rasterization: consecutive bids sweep M with fixed N tile.
    const int m0 = (int)(blockIdx.x & 63) * BM;   // 64 m-tiles
    const int n0 = (int)(blockIdx.x >> 6) * BN;   // 32 n-tiles

    float acc[2][8][4];
#pragma unroll
    for (int mt = 0; mt < 2; mt++)
#pragma unroll
        for (int nt = 0; nt < 8; nt++)
#pragma unroll
            for (int e = 0; e < 4; e++) acc[mt][nt][e] = 0.0f;

    // cp.async per-thread offsets. A: 2048 16B chunks/stage -> 4/thread; B: 1024 -> 2/thread.
    uint32_t aoff[4], adst[4], boff[2], bdst[2];
#pragma unroll
    for (int i = 0; i < 4; i++) {
        int id = tid + i * 512;
        int m = id >> 3, w = id & 7;                   // w: 16B chunk (8 fp16)
        aoff[i] = (uint32_t)((m0 + m) * K_DIM + w * 8);
        adst[i] = (uint32_t)(m * 128 + ((w ^ (m & 7)) << 4));
    }
#pragma unroll
    for (int i = 0; i < 2; i++) {
        int id = tid + i * 512;
        int n = id >> 3, w = id & 7;
        boff[i] = (uint32_t)((n0 + n) * K_DIM + w * 8);
        bdst[i] = (uint32_t)(A_STAGE_BYTES + n * 128 + ((w ^ (n & 7)) << 4));
    }

    // Prologue: prefetch ALL 4 K-chunks (one commit group each).
#pragma unroll
    for (int kc = 0; kc < NCHUNK; kc++) {
        uint32_t stg = sb + (uint32_t)(kc * STAGE_BYTES);
        uint32_t ko = (uint32_t)(kc * KC);
        cp16(stg + adst[0], g_xh + aoff[0] + ko);
        cp16(stg + adst[1], g_xh + aoff[1] + ko);
        cp16(stg + adst[2], g_xh + aoff[2] + ko);
        cp16(stg + adst[3], g_xh + aoff[3] + ko);
        cp16(stg + bdst[0], g_wh + boff[0] + ko);
        cp16(stg + bdst[1], g_wh + boff[1] + ko);
        asm volatile("cp.async.commit_group;" ::: "memory");
    }

    // ldmatrix per-thread row bases.
    // A x4 (per 16-row m-tile): q=lane/8, tr=lane%8; row = R + (q&1)*8 + tr, k-chunk bit = q>>1.
    // B x4 (per 16-row n-group): row = N + (q>=2)*8 + tr, k-chunk bit = q&1.
    const int q = lane >> 3, tr = lane & 7;
    uint32_t arb[2]; int asw[2];
#pragma unroll
    for (int mt = 0; mt < 2; mt++) {
        int row = wm * 32 + mt * 16 + ((q & 1) << 3) + tr;
        arb[mt] = (uint32_t)(row * 128); asw[mt] = row & 7;
    }
    const int ajb = q >> 1;
    uint32_t brb[4]; int bsw[4];
#pragma unroll
    for (int bg = 0; bg < 4; bg++) {
        int row = wn * 64 + bg * 16 + ((q >> 1) << 3) + tr;
        brb[bg] = (uint32_t)(A_STAGE_BYTES + row * 128); bsw[bg] = row & 7;
    }
    const int bjb = q & 1;

#pragma unroll
    for (int kc = 0; kc < NCHUNK; kc++) {
        if (kc == 0)      asm volatile("cp.async.wait_group 3;" ::: "memory");
        else if (kc == 1) asm volatile("cp.async.wait_group 2;" ::: "memory");
        else if (kc == 2) asm volatile("cp.async.wait_group 1;" ::: "memory");
        else              asm volatile("cp.async.wait_group 0;" ::: "memory");
        __syncthreads();

        const uint32_t st = sb + (uint32_t)(kc * STAGE_BYTES);
#pragma unroll
        for (int ks = 0; ks < 4; ks++) {               // 4 x k16 steps per 64-chunk
            uint32_t af[2][4], bf[4][4];
#pragma unroll
            for (int mt = 0; mt < 2; mt++)
                ldsm4(af[mt], st + arb[mt] + (uint32_t)((((2 * ks + ajb) ^ asw[mt])) << 4));
#pragma unroll
            for (int bg = 0; bg < 4; bg++)
                ldsm4(bf[bg], st + brb[bg] + (uint32_t)((((2 * ks + bjb) ^ bsw[bg])) << 4));
#pragma unroll
            for (int mt = 0; mt < 2; mt++)
#pragma unroll
                for (int nt = 0; nt < 8; nt++)
                    mma16(acc[mt][nt], af[mt], bf[nt >> 1][(nt & 1) * 2], bf[nt >> 1][(nt & 1) * 2 + 1]);
        }
    }

    // ---- Epilogue: direct sector-aligned STG.64 from register accumulators ----
    float* op = out + (size_t)(m0 + wm * 32 + g) * N_DIM + (n0 + wn * 64 + 2 * c);
#pragma unroll
    for (int mt = 0; mt < 2; mt++) {
#pragma unroll
        for (int nt = 0; nt < 8; nt++) {
            float2 v0 = make_float2(acc[mt][nt][0], acc[mt][nt][1]);
            float2 v1 = make_float2(acc[mt][nt][2], acc[mt][nt][3]);
            *reinterpret_cast<float2*>(op + (size_t)(mt * 16) * N_DIM + nt * 8) = v0;
            *reinterpret_cast<float2*>(op + (size_t)(mt * 16 + 8) * N_DIM + nt * 8) = v1;
        }
    }
}

// ---------------- launch ----------------
extern "C" void kernel_launch(void* const* d_in, const int* in_sizes, int n_in,
                              void* d_out, int out_size) {
    const float* x = (const float*)d_in[0];
    const float* W = (const float*)d_in[1];
    if (n_in >= 2 && in_sizes[0] == N_DIM * K_DIM && in_sizes[1] == B_DIM * K_DIM) {
        const float* t = x; x = W; W = t;   // defensive order swap
    }
    cudaFuncSetAttribute(slb_gemm, cudaFuncAttributeMaxDynamicSharedMemorySize, SMEM_TOTAL);

    repack_all<<<XBLKS + WBLKS, 256>>>(x, W);
    slb_gemm<<<(B_DIM / BM) * (N_DIM / BN), 512, SMEM_TOTAL>>>((float*)d_out);
}

// round 14
// speedup vs baseline: 6.2153x; 1.2181x over previous
#include <cuda_runtime.h>
#include <cuda_fp16.h>
#include <cstdint>

// Problem dims
#define B_DIM 16384
#define K_DIM 256
#define N_DIM 4096

// Tile config: CTA 128x128, 256 threads, 2 CTAs/SM, warp grid 4(M) x 2(N), warp tile 32x64
#define BM 128
#define BN 128
#define KC 64                       // fp16 per K-chunk (one 128B row per chunk)
#define NCHUNK (K_DIM / KC)         // 4
#define NSTAGE 3
#define A_STAGE_BYTES (BM * 128)    // 16 KB
#define B_STAGE_BYTES (BN * 128)    // 16 KB
#define STAGE_BYTES (A_STAGE_BYTES + B_STAGE_BYTES)  // 32 KB
#define SMEM_TOTAL (NSTAGE * STAGE_BYTES)            // 96 KB -> 2 CTAs/SM fit

// Scratch: fp16(RN) copies. g_wh gathered to [N][K] row-major (k = s*8+cg).
__device__ __half g_xh[B_DIM * K_DIM];   // [B][K]
__device__ __half g_wh[N_DIM * K_DIM];   // [N][K]

// ---------------- helpers ----------------
static __device__ __forceinline__ uint32_t smem_u32(const void* p) {
    uint32_t a;
    asm("{ .reg .u64 t; cvta.to.shared.u64 t, %1; cvt.u32.u64 %0, t; }" : "=r"(a) : "l"(p));
    return a;
}
static __device__ __forceinline__ void ldsm4(uint32_t* r, uint32_t addr) {
    asm volatile("ldmatrix.sync.aligned.m8n8.x4.shared.b16 {%0,%1,%2,%3}, [%4];"
                 : "=r"(r[0]), "=r"(r[1]), "=r"(r[2]), "=r"(r[3]) : "r"(addr));
}
static __device__ __forceinline__ void mma16(float* d, const uint32_t* a, uint32_t b0, uint32_t b1) {
    asm volatile(
        "mma.sync.aligned.m16n8k16.row.col.f32.f16.f16.f32 "
        "{%0,%1,%2,%3}, {%4,%5,%6,%7}, {%8,%9}, {%0,%1,%2,%3};"
        : "+f"(d[0]), "+f"(d[1]), "+f"(d[2]), "+f"(d[3])
        : "r"(a[0]), "r"(a[1]), "r"(a[2]), "r"(a[3]), "r"(b0), "r"(b1));
}
static __device__ __forceinline__ void cp16(uint32_t dst, const __half* src) {
    asm volatile("cp.async.cg.shared.global [%0], [%1], 16;" :: "r"(dst), "l"(src) : "memory");
}

// ---------------- fused repack kernel (fp32 -> fp16 RN, W gather) ----------------
#define XBLKS ((B_DIM * K_DIM / 8) / 256)   // 2048  (8 elems/thread)
#define WBLKS ((N_DIM * K_DIM / 8) / 256)   // 512
__global__ void __launch_bounds__(256) repack_all(const float* __restrict__ x,
                                                  const float* __restrict__ W) {
    int bx = blockIdx.x;
    if (bx < XBLKS) {
        int o = bx * 256 + threadIdx.x;                // 8-float group over x
        const float4* xs = reinterpret_cast<const float4*>(x) + (size_t)o * 2;
        float4 v0 = xs[0], v1 = xs[1];
        __half2* dst = reinterpret_cast<__half2*>(g_xh) + (size_t)o * 4;
        dst[0] = __floats2half2_rn(v0.x, v0.y);
        dst[1] = __floats2half2_rn(v0.z, v0.w);
        dst[2] = __floats2half2_rn(v1.x, v1.y);
        dst[3] = __floats2half2_rn(v1.z, v1.w);
    } else {
        int o = (bx - XBLKS) * 256 + threadIdx.x;      // over N*K/8
        int n = o >> 5, sg = o & 31;                   // slice s = sg, 8 contiguous cg
        const float* src = W + (size_t)sg * (N_DIM * 8) + (size_t)n * 8;
        float4 v0 = *reinterpret_cast<const float4*>(src);
        float4 v1 = *reinterpret_cast<const float4*>(src + 4);
        __half2* dst = reinterpret_cast<__half2*>(g_wh + (size_t)n * K_DIM + sg * 8);
        dst[0] = __floats2half2_rn(v0.x, v0.y);
        dst[1] = __floats2half2_rn(v0.z, v0.w);
        dst[2] = __floats2half2_rn(v1.x, v1.y);
        dst[3] = __floats2half2_rn(v1.z, v1.w);
    }
}

// ---------------- main GEMM kernel ----------------
__global__ void __launch_bounds__(256, 2) slb_gemm(float* __restrict__ out) {
    extern __shared__ char smem[];
    const uint32_t sb = smem_u32(smem);
    const int tid = threadIdx.x;
    const int lane = tid & 31;
    const int wid = tid >> 5;
    const int g = lane >> 2;          // output fragment row group
    const int c = lane & 3;           // output fragment col group
    const int wm = wid & 3;           // warp M index (4)
    const int wn = wid >> 2;          // warp N index (2)

    // m-minor rasterization: consecutive bids sweep M with fixed N tile.
    const int m0 = (int)(blockIdx.x & 127) * BM;   // 128 m-tiles
    const int n0 = (int)(blockIdx.x >> 7) * BN;    // 32 n-tiles

    float acc[2][8][4];
#pragma unroll
    for (int mt = 0; mt < 2; mt++)
#pragma unroll
        for (int nt = 0; nt < 8; nt++)
#pragma unroll
            for (int e = 0; e < 4; e++) acc[mt][nt][e] = 0.0f;

    // cp.async per-thread offsets. A: 1024 16B chunks/stage -> 4/thread; B same.
    uint32_t aoff[4], adst[4], boff[4], bdst[4];
#pragma unroll
    for (int i = 0; i < 4; i++) {
        int id = tid + i * 256;
        int m = id >> 3, w = id & 7;                   // w: 16B chunk (8 fp16)
        aoff[i] = (uint32_t)((m0 + m) * K_DIM + w * 8);
        adst[i] = (uint32_t)(m * 128 + ((w ^ (m & 7)) << 4));
        boff[i] = (uint32_t)((n0 + m) * K_DIM + w * 8);
        bdst[i] = (uint32_t)(A_STAGE_BYTES + m * 128 + ((w ^ (m & 7)) << 4));
    }

#define LOAD_CHUNK(kc, slot)                                                    \
    {                                                                           \
        uint32_t stg_ = sb + (uint32_t)((slot) * STAGE_BYTES);                  \
        uint32_t ko_ = (uint32_t)((kc) * KC);                                   \
        cp16(stg_ + adst[0], g_xh + aoff[0] + ko_);                             \
        cp16(stg_ + adst[1], g_xh + aoff[1] + ko_);                             \
        cp16(stg_ + adst[2], g_xh + aoff[2] + ko_);                             \
        cp16(stg_ + adst[3], g_xh + aoff[3] + ko_);                             \
        cp16(stg_ + bdst[0], g_wh + boff[0] + ko_);                             \
        cp16(stg_ + bdst[1], g_wh + boff[1] + ko_);                             \
        cp16(stg_ + bdst[2], g_wh + boff[2] + ko_);                             \
        cp16(stg_ + bdst[3], g_wh + boff[3] + ko_);                             \
        asm volatile("cp.async.commit_group;" ::: "memory");                    \
    }

    // Prologue: chunks 0..2 into slots 0..2.
    LOAD_CHUNK(0, 0);
    LOAD_CHUNK(1, 1);
    LOAD_CHUNK(2, 2);

    // ldmatrix per-thread row bases.
    const int q = lane >> 3, tr = lane & 7;
    uint32_t arb[2]; int asw[2];
#pragma unroll
    for (int mt = 0; mt < 2; mt++) {
        int row = wm * 32 + mt * 16 + ((q & 1) << 3) + tr;
        arb[mt] = (uint32_t)(row * 128); asw[mt] = row & 7;
    }
    const int ajb = q >> 1;
    uint32_t brb[4]; int bsw[4];
#pragma unroll
    for (int bg = 0; bg < 4; bg++) {
        int row = wn * 64 + bg * 16 + ((q >> 1) << 3) + tr;
        brb[bg] = (uint32_t)(A_STAGE_BYTES + row * 128); bsw[bg] = row & 7;
    }
    const int bjb = q & 1;

#pragma unroll
    for (int kc = 0; kc < NCHUNK; kc++) {
        // Waits: kc0 needs c0 (<=2 pending), kc1 needs c1 (<=1), kc2 needs c2 (<=1
        // since c3 was committed at kc1), kc3 needs c3 (0).
        if (kc == 0)      asm volatile("cp.async.wait_group 2;" ::: "memory");
        else if (kc == 3) asm volatile("cp.async.wait_group 0;" ::: "memory");
        else              asm volatile("cp.async.wait_group 1;" ::: "memory");
        __syncthreads();
        // Chunk 3 -> slot 0. Issued after the kc=1 barrier, which orders it
        // against all iter-0 reads of slot 0.
        if (kc == 1) LOAD_CHUNK(3, 0);

        const uint32_t st = sb + (uint32_t)((kc % NSTAGE) * STAGE_BYTES);
#pragma unroll
        for (int ks = 0; ks < 4; ks++) {               // 4 x k16 steps per 64-chunk
            uint32_t af[2][4], bf[4][4];
#pragma unroll
            for (int mt = 0; mt < 2; mt++)
                ldsm4(af[mt], st + arb[mt] + (uint32_t)((((2 * ks + ajb) ^ asw[mt])) << 4));
#pragma unroll
            for (int bg = 0; bg < 4; bg++)
                ldsm4(bf[bg], st + brb[bg] + (uint32_t)((((2 * ks + bjb) ^ bsw[bg])) << 4));
#pragma unroll
            for (int mt = 0; mt < 2; mt++)
#pragma unroll
                for (int nt = 0; nt < 8; nt++)
                    mma16(acc[mt][nt], af[mt], bf[nt >> 1][(nt & 1) * 2], bf[nt >> 1][(nt & 1) * 2 + 1]);
        }
    }

    // ---- Epilogue: direct sector-aligned STG.64 from register accumulators ----
    float* op = out + (size_t)(m0 + wm * 32 + g) * N_DIM + (n0 + wn * 64 + 2 * c);
#pragma unroll
    for (int mt = 0; mt < 2; mt++) {
#pragma unroll
        for (int nt = 0; nt < 8; nt++) {
            float2 v0 = make_float2(acc[mt][nt][0], acc[mt][nt][1]);
            float2 v1 = make_float2(acc[mt][nt][2], acc[mt][nt][3]);
            *reinterpret_cast<float2*>(op + (size_t)(mt * 16) * N_DIM + nt * 8) = v0;
            *reinterpret_cast<float2*>(op + (size_t)(mt * 16 + 8) * N_DIM + nt * 8) = v1;
        }
    }
}

// ---------------- launch ----------------
extern "C" void kernel_launch(void* const* d_in, const int* in_sizes, int n_in,
                              void* d_out, int out_size) {
    const float* x = (const float*)d_in[0];
    const float* W = (const float*)d_in[1];
    if (n_in >= 2 && in_sizes[0] == N_DIM * K_DIM && in_sizes[1] == B_DIM * K_DIM) {
        const float* t = x; x = W; W = t;   // defensive order swap
    }
    cudaFuncSetAttribute(slb_gemm, cudaFuncAttributeMaxDynamicSharedMemorySize, SMEM_TOTAL);

    repack_all<<<XBLKS + WBLKS, 256>>>(x, W);
    slb_gemm<<<(B_DIM / BM) * (N_DIM / BN), 256, SMEM_TOTAL>>>((float*)d_out);
}